// round 2
// baseline (speedup 1.0000x reference)
#include <cuda_runtime.h>
#include <cstdint>
#include <cstddef>

typedef unsigned long long ull;

#define T_   2048
#define B_   128
#define IN_  128
#define H_   256
#define G4_  1024
#define OUT_ 64

#define BG_  16   // batch groups
#define HCN_ 8    // hidden-slice CTAs per batch group
#define BC_  8    // batches per group

#define WPAD 132  // padded row stride (floats) for k-major W tile

// dynamic smem for k_rec: wT[256][132] + hT[256][8] + red[8][32][32] + fin[128][9]
#define REC_SMEM ((256 * WPAD + 256 * 8 + 8 * 32 * 32 + 128 * 9) * 4)
// dynamic smem for k_out: wo[64][256] + rs[32][132]
#define OUT_SMEM ((64 * 256 + 32 * 132) * 4)

// ---------------- device scratch (static, allocation-free) ----------------
__device__ float    d_xg[(size_t)T_ * B_ * G4_];    // 1 GB  [t][bg][hc][bb][col]
__device__ float    d_rbuf[(size_t)T_ * B_ * H_];   // 256 MB [t][b][h]
__device__ float    d_hTg[2 * BG_ * H_ * BC_];      // 256 KB [par][bg][h][bb]
__device__ unsigned d_flags[T_ * BG_ * HCN_];       // 1 MB
__device__ unsigned d_runid;

// ---------------- f32x2 helpers (sm_100+ packed fp32) ----------------
__device__ __forceinline__ ull pack2(float x) {
    unsigned xi = __float_as_uint(x);
    ull r;
    asm("mov.b64 %0, {%1, %1};" : "=l"(r) : "r"(xi));
    return r;
}
__device__ __forceinline__ ull ffma2(ull a, ull b, ull c) {
    ull d;
    asm("fma.rn.f32x2 %0, %1, %2, %3;" : "=l"(d) : "l"(a), "l"(b), "l"(c));
    return d;
}
__device__ __forceinline__ ull fadd2(ull a, ull b) {
    ull d;
    asm("add.rn.f32x2 %0, %1, %2;" : "=l"(d) : "l"(a), "l"(b));
    return d;
}
__device__ __forceinline__ void unpack2(ull v, float& lo, float& hi) {
    unsigned l, h;
    asm("mov.b64 {%0, %1}, %2;" : "=r"(l), "=r"(h) : "l"(v));
    lo = __uint_as_float(l);
    hi = __uint_as_float(h);
}
__device__ __forceinline__ float sigm(float x) {
    return 1.0f / (1.0f + __expf(-x));
}

// ---------------- run-id bump (replay-safe flag generations) ----------------
__global__ void k_init() { d_runid = d_runid + 1u; }

// ---------------- kernel 1: xg = x @ W_ih^T + b_ih + b_hh (permuted) -------
// grid (8 hc, 2048 t), 256 threads. Output block per (t,bg,hc): [bb][col],
// col = hh*4 + gate, W row R = gate*256 + hc*32 + hh.
__global__ __launch_bounds__(256, 1) void k_xg(const float* __restrict__ x,
                                               const float* __restrict__ W_ih,
                                               const float* __restrict__ b_ih,
                                               const float* __restrict__ b_hh) {
    __shared__ float xs[32 * WPAD];
    __shared__ float ws[32 * WPAD];
    const int hc = blockIdx.x;
    const int t = blockIdx.y;
    const int u = threadIdx.x;
    const int tm = u & 15;   // batch group (bg!) — covers b = tm*8 .. tm*8+7
    const int tn = u >> 4;   // col group — covers col = tn*8 .. tn*8+7

    ull acc[8][4];
#pragma unroll
    for (int j = 0; j < 8; j++)
#pragma unroll
        for (int p = 0; p < 4; p++) acc[j][p] = 0ull;

    // staging roles
    const int bs = u >> 1, half = u & 1;
    const int colS = u >> 1;
    const int RS = (colS & 3) * H_ + hc * 32 + (colS >> 2);
    const float* xsrc = x + ((size_t)t * B_ + bs) * IN_ + half * 16;
    const float* wsrc = W_ih + (size_t)RS * IN_ + half * 16;

    for (int kc = 0; kc < IN_; kc += 32) {
#pragma unroll
        for (int q = 0; q < 4; q++) {
            float4 v = *(const float4*)(xsrc + kc + q * 4);
            int kl = half * 16 + q * 4;
            xs[(kl + 0) * WPAD + bs] = v.x;
            xs[(kl + 1) * WPAD + bs] = v.y;
            xs[(kl + 2) * WPAD + bs] = v.z;
            xs[(kl + 3) * WPAD + bs] = v.w;
            float4 w = *(const float4*)(wsrc + kc + q * 4);
            ws[(kl + 0) * WPAD + colS] = w.x;
            ws[(kl + 1) * WPAD + colS] = w.y;
            ws[(kl + 2) * WPAD + colS] = w.z;
            ws[(kl + 3) * WPAD + colS] = w.w;
        }
        __syncthreads();
#pragma unroll 8
        for (int kk = 0; kk < 32; kk++) {
            const float* xr = &xs[kk * WPAD + tm * 8];
            ulonglong2 xa = *(const ulonglong2*)xr;
            ulonglong2 xb = *(const ulonglong2*)(xr + 4);
            ull xp0 = xa.x, xp1 = xa.y, xp2 = xb.x, xp3 = xb.y;
            const float* wr = &ws[kk * WPAD + tn * 8];
            float4 wa = *(const float4*)wr;
            float4 wb = *(const float4*)(wr + 4);
            float wv[8] = {wa.x, wa.y, wa.z, wa.w, wb.x, wb.y, wb.z, wb.w};
#pragma unroll
            for (int j = 0; j < 8; j++) {
                ull wj = pack2(wv[j]);
                acc[j][0] = ffma2(wj, xp0, acc[j][0]);
                acc[j][1] = ffma2(wj, xp1, acc[j][1]);
                acc[j][2] = ffma2(wj, xp2, acc[j][2]);
                acc[j][3] = ffma2(wj, xp3, acc[j][3]);
            }
        }
        __syncthreads();
    }
    // epilogue: add biases, store permuted
    size_t base = (((size_t)t * BG_ + tm) * HCN_ + hc) * 1024;
#pragma unroll
    for (int j = 0; j < 8; j++) {
        int col = tn * 8 + j;
        int R = (col & 3) * H_ + hc * 32 + (col >> 2);
        float bv = b_ih[R] + b_hh[R];
#pragma unroll
        for (int p = 0; p < 4; p++) {
            float lo, hi;
            unpack2(acc[j][p], lo, hi);
            d_xg[base + (size_t)(2 * p) * 128 + col] = lo + bv;
            d_xg[base + (size_t)(2 * p + 1) * 128 + col] = hi + bv;
        }
    }
}

// ---------------- kernel 2: persistent recurrence ----------------
// 128 CTAs: blockIdx.x = bg*8 + hc. CTA owns hidden units hc*32..hc*32+31
// (all 4 gates) for batches bg*8..bg*8+7. W slice k-major in smem.
__global__ __launch_bounds__(256, 1) void k_rec(const float* __restrict__ W_hh) {
    extern __shared__ float sm[];
    float* wT = sm;                    // [256][WPAD]  wT[k*WPAD + r], r = hh*4+g
    float* hT = wT + 256 * WPAD;       // [256][8]
    float* red = hT + 256 * 8;         // [8][32][32]  swizzled partials
    float* fin = red + 8 * 32 * 32;    // [128][9]

    const int u = threadIdx.x;
    const int bg = blockIdx.x >> 3;
    const int hc = blockIdx.x & 7;
    const unsigned runid = d_runid;

    // stage W slice (once): global row R = g*256 + hc*32 + hh  ->  smem row r = hh*4+g
    {
        int w = u >> 5, l = u & 31;
        for (int rr = w * 16; rr < w * 16 + 16; rr++) {
            int g = rr & 3, hh = rr >> 2;
            const float* src = W_hh + ((size_t)(g * H_ + hc * 32 + hh)) * H_ + l * 8;
            float4 a = *(const float4*)src;
            float4 b4 = *(const float4*)(src + 4);
            int k0 = l * 8;
            wT[(k0 + 0) * WPAD + rr] = a.x;
            wT[(k0 + 1) * WPAD + rr] = a.y;
            wT[(k0 + 2) * WPAD + rr] = a.z;
            wT[(k0 + 3) * WPAD + rr] = a.w;
            wT[(k0 + 4) * WPAD + rr] = b4.x;
            wT[(k0 + 5) * WPAD + rr] = b4.y;
            wT[(k0 + 6) * WPAD + rr] = b4.z;
            wT[(k0 + 7) * WPAD + rr] = b4.w;
        }
    }

    const int tx = u & 31, kz = u >> 5;  // GEMM role: rows 4tx..4tx+3, K-chunk kz
    const int hh = u & 31, bb = u >> 5;  // epilogue role: hidden hh, batch bb
    float c = 0.0f;
    const size_t xgbase = ((size_t)bg * HCN_ + hc) * 1024 + (size_t)bb * 128 + hh * 4;

    for (int t = 0; t < T_; t++) {
        // --- wait for previous step's h from all 8 peers (flag gen = runid) ---
        if (t > 0 && u < 8) {
            volatile unsigned* f = &d_flags[((size_t)(t - 1) * BG_ + bg) * HCN_ + u];
            while (*f != runid) {}
            __threadfence();  // acquire side of the fence-fence sync
        }
        __syncthreads();

        // --- load h tile [k][b] (already k-major in d_hTg) ---
        {
            float4 a, b4;
            if (t > 0) {
                const float* hp = &d_hTg[((((t - 1) & 1) * BG_ + bg) * H_ + u) * BC_];
                a = *(const float4*)hp;
                b4 = *(const float4*)(hp + 4);
            } else {
                a = make_float4(0.f, 0.f, 0.f, 0.f);
                b4 = a;
            }
            *(float4*)&hT[u * 8] = a;
            *(float4*)&hT[u * 8 + 4] = b4;
        }
        __syncthreads();

        // --- GEMM: 4 rows x 8 batches over K-chunk of 32 ---
        ull acc[4][4];
#pragma unroll
        for (int g = 0; g < 4; g++)
#pragma unroll
            for (int p = 0; p < 4; p++) acc[g][p] = 0ull;

        const float* wbase = &wT[(kz * 32) * WPAD + 4 * tx];
        const float* hbase = &hT[(kz * 32) * 8];
#pragma unroll 4
        for (int kk = 0; kk < 32; kk++) {
            float4 w4 = *(const float4*)(wbase + kk * WPAD);
            ulonglong2 hA = *(const ulonglong2*)(hbase + kk * 8);
            ulonglong2 hB = *(const ulonglong2*)(hbase + kk * 8 + 4);
            ull h0 = hA.x, h1 = hA.y, h2 = hB.x, h3 = hB.y;
            ull w0 = pack2(w4.x), w1 = pack2(w4.y), w2 = pack2(w4.z), w3 = pack2(w4.w);
            acc[0][0] = ffma2(w0, h0, acc[0][0]);
            acc[0][1] = ffma2(w0, h1, acc[0][1]);
            acc[0][2] = ffma2(w0, h2, acc[0][2]);
            acc[0][3] = ffma2(w0, h3, acc[0][3]);
            acc[1][0] = ffma2(w1, h0, acc[1][0]);
            acc[1][1] = ffma2(w1, h1, acc[1][1]);
            acc[1][2] = ffma2(w1, h2, acc[1][2]);
            acc[1][3] = ffma2(w1, h3, acc[1][3]);
            acc[2][0] = ffma2(w2, h0, acc[2][0]);
            acc[2][1] = ffma2(w2, h1, acc[2][1]);
            acc[2][2] = ffma2(w2, h2, acc[2][2]);
            acc[2][3] = ffma2(w2, h3, acc[2][3]);
            acc[3][0] = ffma2(w3, h0, acc[3][0]);
            acc[3][1] = ffma2(w3, h1, acc[3][1]);
            acc[3][2] = ffma2(w3, h2, acc[3][2]);
            acc[3][3] = ffma2(w3, h3, acc[3][3]);
        }

        // prefetch xg for the epilogue (hides DRAM latency behind reduction)
        const float* xgp = &d_xg[(size_t)t * (BG_ * HCN_ * 1024) + xgbase];
        float4 xg4 = *(const float4*)xgp;

        // --- scatter partials, conflict-free swizzle ---
        {
            float* rb = &red[(kz * 32 + tx) * 32];
#pragma unroll
            for (int g = 0; g < 4; g++)
#pragma unroll
                for (int hv = 0; hv < 2; hv++) {
                    int j = g * 2 + hv;
                    ulonglong2 v;
                    v.x = acc[g][2 * hv];
                    v.y = acc[g][2 * hv + 1];
                    *(ulonglong2*)&rb[((j + tx) & 7) * 4] = v;
                }
        }
        __syncthreads();

        // --- cross-K reduction: thread (txr, j) sums one swizzled vec4 over 8 chunks ---
        {
            int txr = u >> 3, j = u & 7;
            int off = txr * 32 + ((j + txr) & 7) * 4;
            ull s0 = 0ull, s1 = 0ull;
#pragma unroll
            for (int z = 0; z < 8; z++) {
                ulonglong2 v = *(const ulonglong2*)&red[z * 1024 + off];
                s0 = fadd2(s0, v.x);
                s1 = fadd2(s1, v.y);
            }
            int r = txr * 4 + (j >> 1);
            int b0 = (j & 1) * 4;
            float f0, f1, f2, f3;
            unpack2(s0, f0, f1);
            unpack2(s1, f2, f3);
            fin[r * 9 + b0 + 0] = f0;
            fin[r * 9 + b0 + 1] = f1;
            fin[r * 9 + b0 + 2] = f2;
            fin[r * 9 + b0 + 3] = f3;
        }
        __syncthreads();

        // --- gate nonlinearity + state update (thread = (hh, bb)) ---
        {
            float si = fin[(hh * 4 + 0) * 9 + bb] + xg4.x;
            float sf = fin[(hh * 4 + 1) * 9 + bb] + xg4.y;
            float sg = fin[(hh * 4 + 2) * 9 + bb] + xg4.z;
            float so = fin[(hh * 4 + 3) * 9 + bb] + xg4.w;
            float iv = sigm(si);
            float fv = sigm(sf);
            float gv = tanhf(sg);
            float ov = sigm(so);
            c = fv * c + iv * gv;
            float hval = ov * tanhf(c);
            d_rbuf[((size_t)t * B_ + bg * BC_ + bb) * H_ + hc * 32 + hh] = hval;
            d_hTg[(((t & 1) * BG_ + bg) * H_ + hc * 32 + hh) * BC_ + bb] = hval;
        }
        __threadfence();   // release: h visible at gpu scope before flag
        __syncthreads();   // all threads' stores+fences done before flag
        if (u == 0) {
            *(volatile unsigned*)&d_flags[((size_t)t * BG_ + bg) * HCN_ + hc] = runid;
        }
    }
}

// ---------------- kernel 3: out = r_out @ W_out^T + b_out ----------------
__global__ __launch_bounds__(256, 1) void k_out(const float* __restrict__ W_out,
                                                const float* __restrict__ b_out,
                                                float* __restrict__ out) {
    extern __shared__ float sm[];
    float* wo = sm;              // [64][256] row-major copy of W_out
    float* rs = sm + 64 * 256;   // [32][WPAD]
    const int t = blockIdx.x;
    const int u = threadIdx.x;

    for (int i = u; i < 64 * 256 / 4; i += 256)
        *(float4*)&wo[i * 4] = *(const float4*)&W_out[i * 4];

    const int bq = u & 15, oq = u >> 4;
    ull acc[4][4];
#pragma unroll
    for (int j = 0; j < 4; j++)
#pragma unroll
        for (int p = 0; p < 4; p++) acc[j][p] = 0ull;

    const int bs = u >> 1, half = u & 1;
    const float* rsrc = d_rbuf + ((size_t)t * B_ + bs) * H_ + half * 16;
    __syncthreads();

    for (int kc = 0; kc < H_; kc += 32) {
#pragma unroll
        for (int q = 0; q < 4; q++) {
            float4 v = *(const float4*)(rsrc + kc + q * 4);
            int kl = half * 16 + q * 4;
            rs[(kl + 0) * WPAD + bs] = v.x;
            rs[(kl + 1) * WPAD + bs] = v.y;
            rs[(kl + 2) * WPAD + bs] = v.z;
            rs[(kl + 3) * WPAD + bs] = v.w;
        }
        __syncthreads();
#pragma unroll 4
        for (int kk = 0; kk < 32; kk++) {
            int k = kc + kk;
            const float* xr = &rs[kk * WPAD + bq * 8];
            ulonglong2 xa = *(const ulonglong2*)xr;
            ulonglong2 xb = *(const ulonglong2*)(xr + 4);
            ull xp0 = xa.x, xp1 = xa.y, xp2 = xb.x, xp3 = xb.y;
#pragma unroll
            for (int j = 0; j < 4; j++) {
                ull wj = pack2(wo[(oq * 4 + j) * 256 + k]);
                acc[j][0] = ffma2(wj, xp0, acc[j][0]);
                acc[j][1] = ffma2(wj, xp1, acc[j][1]);
                acc[j][2] = ffma2(wj, xp2, acc[j][2]);
                acc[j][3] = ffma2(wj, xp3, acc[j][3]);
            }
        }
        __syncthreads();
    }
#pragma unroll
    for (int j = 0; j < 4; j++) {
        int o = oq * 4 + j;
        float bv = b_out[o];
#pragma unroll
        for (int p = 0; p < 4; p++) {
            float lo, hi;
            unpack2(acc[j][p], lo, hi);
            int b0 = bq * 8 + 2 * p;
            out[((size_t)t * B_ + b0) * OUT_ + o] = lo + bv;
            out[((size_t)t * B_ + b0 + 1) * OUT_ + o] = hi + bv;
        }
    }
}

// ---------------- launcher ----------------
extern "C" void kernel_launch(void* const* d_in, const int* in_sizes, int n_in,
                              void* d_out, int out_size) {
    const float* x     = (const float*)d_in[0];
    const float* W_ih  = (const float*)d_in[1];
    const float* W_hh  = (const float*)d_in[2];
    const float* b_ih  = (const float*)d_in[3];
    const float* b_hh  = (const float*)d_in[4];
    const float* W_out = (const float*)d_in[5];
    const float* b_out = (const float*)d_in[6];
    float* out = (float*)d_out;

    cudaFuncSetAttribute(k_rec, cudaFuncAttributeMaxDynamicSharedMemorySize, REC_SMEM);
    cudaFuncSetAttribute(k_out, cudaFuncAttributeMaxDynamicSharedMemorySize, OUT_SMEM);

    k_init<<<1, 1>>>();
    k_xg<<<dim3(HCN_, T_), 256>>>(x, W_ih, b_ih, b_hh);
    k_rec<<<BG_ * HCN_, 256, REC_SMEM>>>(W_hh);
    k_out<<<T_, 256, OUT_SMEM>>>(W_out, b_out, out);
}

// round 3
// speedup vs baseline: 1.6205x; 1.6205x over previous
#include <cuda_runtime.h>
#include <cstdint>
#include <cstddef>

typedef unsigned long long ull;

#define T_   2048
#define B_   128
#define IN_  128
#define H_   256
#define G4_  1024
#define OUT_ 64

#define BG_  16   // batch groups
#define HCN_ 8    // hidden-slice CTAs per batch group
#define BC_  8    // batches per group

#define WPAD 132  // padded row stride (floats) for k-major W tile

#define NKZ  16   // K chunks in k_rec
#define KCH  16   // K per chunk

// dynamic smem for k_rec: wT[256][132] + hT[256][8] + red[16][32][32] + fin[128][9]
#define REC_SMEM ((256 * WPAD + 256 * 8 + NKZ * 32 * 32 + 128 * 9) * 4)
// dynamic smem for k_out: wo[64][256] + rs[32][132]
#define OUT_SMEM ((64 * 256 + 32 * WPAD) * 4)

// ---------------- device scratch (static, allocation-free) ----------------
__device__ float    d_xg[(size_t)T_ * B_ * G4_];    // 1 GB  [t][bg][hc][bb][col]
__device__ float    d_rbuf[(size_t)T_ * B_ * H_];   // 256 MB [t][b][h]
__device__ float    d_hTg[2 * BG_ * H_ * BC_];      // 256 KB [par][bg][h][bb]
__device__ unsigned d_flags[T_ * BG_ * HCN_];       // 1 MB
__device__ unsigned d_runid;

// ---------------- f32x2 helpers (sm_100+ packed fp32) ----------------
__device__ __forceinline__ ull pack2(float x) {
    unsigned xi = __float_as_uint(x);
    ull r;
    asm("mov.b64 %0, {%1, %1};" : "=l"(r) : "r"(xi));
    return r;
}
__device__ __forceinline__ ull ffma2(ull a, ull b, ull c) {
    ull d;
    asm("fma.rn.f32x2 %0, %1, %2, %3;" : "=l"(d) : "l"(a), "l"(b), "l"(c));
    return d;
}
__device__ __forceinline__ ull fadd2(ull a, ull b) {
    ull d;
    asm("add.rn.f32x2 %0, %1, %2;" : "=l"(d) : "l"(a), "l"(b));
    return d;
}
__device__ __forceinline__ void unpack2(ull v, float& lo, float& hi) {
    unsigned l, h;
    asm("mov.b64 {%0, %1}, %2;" : "=r"(l), "=r"(h) : "l"(v));
    lo = __uint_as_float(l);
    hi = __uint_as_float(h);
}
__device__ __forceinline__ float sigm(float x) {
    return 1.0f / (1.0f + __expf(-x));
}

// ---------------- run-id bump (replay-safe flag generations) ----------------
__global__ void k_init() { d_runid = d_runid + 1u; }

// ---------------- kernel 1: xg = x @ W_ih^T + b_ih + b_hh (permuted) -------
// grid (8 hc, 2048 t), 256 threads. Output block per (t,bg,hc): [bb][col],
// col = hh*4 + gate, W row R = gate*256 + hc*32 + hh.
__global__ __launch_bounds__(256, 2) void k_xg(const float* __restrict__ x,
                                               const float* __restrict__ W_ih,
                                               const float* __restrict__ b_ih,
                                               const float* __restrict__ b_hh) {
    __shared__ float xs[32 * WPAD];
    __shared__ float ws[32 * WPAD];
    const int hc = blockIdx.x;
    const int t = blockIdx.y;
    const int u = threadIdx.x;
    const int tm = u & 15;   // batch group — covers b = tm*8 .. tm*8+7
    const int tn = u >> 4;   // col group — covers col = tn*8 .. tn*8+7

    ull acc[8][4];
#pragma unroll
    for (int j = 0; j < 8; j++)
#pragma unroll
        for (int p = 0; p < 4; p++) acc[j][p] = 0ull;

    // staging roles
    const int bs = u >> 1, half = u & 1;
    const int colS = u >> 1;
    const int RS = (colS & 3) * H_ + hc * 32 + (colS >> 2);
    const float* xsrc = x + ((size_t)t * B_ + bs) * IN_ + half * 16;
    const float* wsrc = W_ih + (size_t)RS * IN_ + half * 16;

    for (int kc = 0; kc < IN_; kc += 32) {
#pragma unroll
        for (int q = 0; q < 4; q++) {
            float4 v = *(const float4*)(xsrc + kc + q * 4);
            int kl = half * 16 + q * 4;
            xs[(kl + 0) * WPAD + bs] = v.x;
            xs[(kl + 1) * WPAD + bs] = v.y;
            xs[(kl + 2) * WPAD + bs] = v.z;
            xs[(kl + 3) * WPAD + bs] = v.w;
            float4 w = *(const float4*)(wsrc + kc + q * 4);
            ws[(kl + 0) * WPAD + colS] = w.x;
            ws[(kl + 1) * WPAD + colS] = w.y;
            ws[(kl + 2) * WPAD + colS] = w.z;
            ws[(kl + 3) * WPAD + colS] = w.w;
        }
        __syncthreads();
#pragma unroll 8
        for (int kk = 0; kk < 32; kk++) {
            const float* xr = &xs[kk * WPAD + tm * 8];
            ulonglong2 xa = *(const ulonglong2*)xr;
            ulonglong2 xb = *(const ulonglong2*)(xr + 4);
            ull xp0 = xa.x, xp1 = xa.y, xp2 = xb.x, xp3 = xb.y;
            const float* wr = &ws[kk * WPAD + tn * 8];
            float4 wa = *(const float4*)wr;
            float4 wb = *(const float4*)(wr + 4);
            float wv[8] = {wa.x, wa.y, wa.z, wa.w, wb.x, wb.y, wb.z, wb.w};
#pragma unroll
            for (int j = 0; j < 8; j++) {
                ull wj = pack2(wv[j]);
                acc[j][0] = ffma2(wj, xp0, acc[j][0]);
                acc[j][1] = ffma2(wj, xp1, acc[j][1]);
                acc[j][2] = ffma2(wj, xp2, acc[j][2]);
                acc[j][3] = ffma2(wj, xp3, acc[j][3]);
            }
        }
        __syncthreads();
    }
    // epilogue: add biases, store permuted
    size_t base = (((size_t)t * BG_ + tm) * HCN_ + hc) * 1024;
#pragma unroll
    for (int j = 0; j < 8; j++) {
        int col = tn * 8 + j;
        int R = (col & 3) * H_ + hc * 32 + (col >> 2);
        float bv = b_ih[R] + b_hh[R];
#pragma unroll
        for (int p = 0; p < 4; p++) {
            float lo, hi;
            unpack2(acc[j][p], lo, hi);
            d_xg[base + (size_t)(2 * p) * 128 + col] = lo + bv;
            d_xg[base + (size_t)(2 * p + 1) * 128 + col] = hi + bv;
        }
    }
}

// ---------------- kernel 2: persistent recurrence (512 threads) ----------------
// 128 CTAs: blockIdx.x = bg*8 + hc. CTA owns hidden units hc*32..hc*32+31
// (all 4 gates) for batches bg*8..bg*8+7. W slice k-major in smem.
// 16 warps: GEMM role (tx = rows 4tx..4tx+3, kz = K-chunk of 16).
__global__ __launch_bounds__(512, 1) void k_rec(const float* __restrict__ W_hh) {
    extern __shared__ float sm[];
    float* wT = sm;                    // [256][WPAD]  wT[k*WPAD + r], r = hh*4+g
    float* hT = wT + 256 * WPAD;       // [256][8]
    float* red = hT + 256 * 8;         // [16][32][32]  swizzled partials
    float* fin = red + NKZ * 32 * 32;  // [128][9]

    const int u = threadIdx.x;
    const int bg = blockIdx.x >> 3;
    const int hc = blockIdx.x & 7;
    const unsigned runid = d_runid;

    // stage W slice (once): global row R = g*256 + hc*32 + hh  ->  smem row r = hh*4+g
    {
        int w = u >> 5, l = u & 31;
        for (int rr = w * 8; rr < w * 8 + 8; rr++) {
            int g = rr & 3, hh = rr >> 2;
            const float* src = W_hh + ((size_t)(g * H_ + hc * 32 + hh)) * H_ + l * 8;
            float4 a = *(const float4*)src;
            float4 b4 = *(const float4*)(src + 4);
            int k0 = l * 8;
            wT[(k0 + 0) * WPAD + rr] = a.x;
            wT[(k0 + 1) * WPAD + rr] = a.y;
            wT[(k0 + 2) * WPAD + rr] = a.z;
            wT[(k0 + 3) * WPAD + rr] = a.w;
            wT[(k0 + 4) * WPAD + rr] = b4.x;
            wT[(k0 + 5) * WPAD + rr] = b4.y;
            wT[(k0 + 6) * WPAD + rr] = b4.z;
            wT[(k0 + 7) * WPAD + rr] = b4.w;
        }
    }

    const int tx = u & 31, kz = u >> 5;  // GEMM role: rows 4tx..4tx+3, K-chunk kz
    const int hh = u & 31, bb = u >> 5;  // epilogue role (u<256): hidden hh, batch bb
    float c = 0.0f;
    const size_t xgbase = ((size_t)bg * HCN_ + hc) * 1024 + (size_t)bb * 128 + hh * 4;

    for (int t = 0; t < T_; t++) {
        // --- wait for previous step's h from all 8 peers (flag gen = runid) ---
        if (t > 0 && u < 8) {
            volatile unsigned* f = &d_flags[((size_t)(t - 1) * BG_ + bg) * HCN_ + u];
            while (*f != runid) {}
            __threadfence();  // acquire
        }
        __syncthreads();

        // --- load h tile [k][b] (already k-major in d_hTg); 512 threads x float4 ---
        {
            float4 a;
            if (t > 0) {
                const float* hp = &d_hTg[(((size_t)((t - 1) & 1) * BG_ + bg) * H_) * BC_ + u * 4];
                a = *(const float4*)hp;
            } else {
                a = make_float4(0.f, 0.f, 0.f, 0.f);
            }
            *(float4*)&hT[u * 4] = a;
        }
        __syncthreads();

        // --- xg prefetch early: DRAM latency hides under the GEMM ---
        float4 xg4 = make_float4(0.f, 0.f, 0.f, 0.f);
        if (u < 256) {
            const float* xgp = &d_xg[(size_t)t * (BG_ * HCN_ * 1024) + xgbase];
            xg4 = *(const float4*)xgp;
        }

        // --- GEMM: 4 rows x 8 batches over K-chunk of 16 ---
        ull acc[4][4];
#pragma unroll
        for (int g = 0; g < 4; g++)
#pragma unroll
            for (int p = 0; p < 4; p++) acc[g][p] = 0ull;

        const float* wbase = &wT[(kz * KCH) * WPAD + 4 * tx];
        const float* hbase = &hT[(kz * KCH) * 8];
#pragma unroll
        for (int kk = 0; kk < KCH; kk++) {
            float4 w4 = *(const float4*)(wbase + kk * WPAD);
            ulonglong2 hA = *(const ulonglong2*)(hbase + kk * 8);
            ulonglong2 hB = *(const ulonglong2*)(hbase + kk * 8 + 4);
            ull h0 = hA.x, h1 = hA.y, h2 = hB.x, h3 = hB.y;
            ull w0 = pack2(w4.x), w1 = pack2(w4.y), w2 = pack2(w4.z), w3 = pack2(w4.w);
            acc[0][0] = ffma2(w0, h0, acc[0][0]);
            acc[0][1] = ffma2(w0, h1, acc[0][1]);
            acc[0][2] = ffma2(w0, h2, acc[0][2]);
            acc[0][3] = ffma2(w0, h3, acc[0][3]);
            acc[1][0] = ffma2(w1, h0, acc[1][0]);
            acc[1][1] = ffma2(w1, h1, acc[1][1]);
            acc[1][2] = ffma2(w1, h2, acc[1][2]);
            acc[1][3] = ffma2(w1, h3, acc[1][3]);
            acc[2][0] = ffma2(w2, h0, acc[2][0]);
            acc[2][1] = ffma2(w2, h1, acc[2][1]);
            acc[2][2] = ffma2(w2, h2, acc[2][2]);
            acc[2][3] = ffma2(w2, h3, acc[2][3]);
            acc[3][0] = ffma2(w3, h0, acc[3][0]);
            acc[3][1] = ffma2(w3, h1, acc[3][1]);
            acc[3][2] = ffma2(w3, h2, acc[3][2]);
            acc[3][3] = ffma2(w3, h3, acc[3][3]);
        }

        // --- scatter partials, conflict-free swizzle ---
        {
            float* rb = &red[(kz * 32 + tx) * 32];
#pragma unroll
            for (int g = 0; g < 4; g++)
#pragma unroll
                for (int hv = 0; hv < 2; hv++) {
                    int j = g * 2 + hv;
                    ulonglong2 v;
                    v.x = acc[g][2 * hv];
                    v.y = acc[g][2 * hv + 1];
                    *(ulonglong2*)&rb[((j + tx) & 7) * 4] = v;
                }
        }
        __syncthreads();

        // --- cross-K reduction: thread (txr, j) sums one swizzled vec4 over 16 chunks ---
        if (u < 256) {
            int txr = u >> 3, j = u & 7;
            int off = txr * 32 + ((j + txr) & 7) * 4;
            ull s0 = 0ull, s1 = 0ull;
#pragma unroll
            for (int z = 0; z < NKZ; z++) {
                ulonglong2 v = *(const ulonglong2*)&red[z * 1024 + off];
                s0 = fadd2(s0, v.x);
                s1 = fadd2(s1, v.y);
            }
            int r = txr * 4 + (j >> 1);
            int b0 = (j & 1) * 4;
            float f0, f1, f2, f3;
            unpack2(s0, f0, f1);
            unpack2(s1, f2, f3);
            fin[r * 9 + b0 + 0] = f0;
            fin[r * 9 + b0 + 1] = f1;
            fin[r * 9 + b0 + 2] = f2;
            fin[r * 9 + b0 + 3] = f3;
        }
        __syncthreads();

        // --- gate nonlinearity + state update (thread = (hh, bb), u<256) ---
        if (u < 256) {
            float si = fin[(hh * 4 + 0) * 9 + bb] + xg4.x;
            float sf = fin[(hh * 4 + 1) * 9 + bb] + xg4.y;
            float sg = fin[(hh * 4 + 2) * 9 + bb] + xg4.z;
            float so = fin[(hh * 4 + 3) * 9 + bb] + xg4.w;
            float iv = sigm(si);
            float fv = sigm(sf);
            float gv = tanhf(sg);
            float ov = sigm(so);
            c = fv * c + iv * gv;
            float hval = ov * tanhf(c);
            d_rbuf[((size_t)t * B_ + bg * BC_ + bb) * H_ + hc * 32 + hh] = hval;
            d_hTg[((((size_t)(t & 1)) * BG_ + bg) * H_ + hc * 32 + hh) * BC_ + bb] = hval;
        }
        __syncthreads();   // all epilogue stores issued before release
        if (u == 0) {
            __threadfence();  // release (single thread, after CTA barrier)
            *(volatile unsigned*)&d_flags[((size_t)t * BG_ + bg) * HCN_ + hc] = runid;
        }
    }
}

// ---------------- kernel 3: out = r_out @ W_out^T + b_out ----------------
__global__ __launch_bounds__(256, 2) void k_out(const float* __restrict__ W_out,
                                                const float* __restrict__ b_out,
                                                float* __restrict__ out) {
    extern __shared__ float sm[];
    float* wo = sm;              // [64][256] row-major copy of W_out
    float* rs = sm + 64 * 256;   // [32][WPAD]
    const int t = blockIdx.x;
    const int u = threadIdx.x;

    for (int i = u; i < 64 * 256 / 4; i += 256)
        *(float4*)&wo[i * 4] = *(const float4*)&W_out[i * 4];

    const int bq = u & 15, oq = u >> 4;
    ull acc[4][4];
#pragma unroll
    for (int j = 0; j < 4; j++)
#pragma unroll
        for (int p = 0; p < 4; p++) acc[j][p] = 0ull;

    const int bs = u >> 1, half = u & 1;
    const float* rsrc = d_rbuf + ((size_t)t * B_ + bs) * H_ + half * 16;
    __syncthreads();

    for (int kc = 0; kc < H_; kc += 32) {
#pragma unroll
        for (int q = 0; q < 4; q++) {
            float4 v = *(const float4*)(rsrc + kc + q * 4);
            int kl = half * 16 + q * 4;
            rs[(kl + 0) * WPAD + bs] = v.x;
            rs[(kl + 1) * WPAD + bs] = v.y;
            rs[(kl + 2) * WPAD + bs] = v.z;
            rs[(kl + 3) * WPAD + bs] = v.w;
        }
        __syncthreads();
#pragma unroll 4
        for (int kk = 0; kk < 32; kk++) {
            int k = kc + kk;
            const float* xr = &rs[kk * WPAD + bq * 8];
            ulonglong2 xa = *(const ulonglong2*)xr;
            ulonglong2 xb = *(const ulonglong2*)(xr + 4);
            ull xp0 = xa.x, xp1 = xa.y, xp2 = xb.x, xp3 = xb.y;
#pragma unroll
            for (int j = 0; j < 4; j++) {
                ull wj = pack2(wo[(oq * 4 + j) * 256 + k]);
                acc[j][0] = ffma2(wj, xp0, acc[j][0]);
                acc[j][1] = ffma2(wj, xp1, acc[j][1]);
                acc[j][2] = ffma2(wj, xp2, acc[j][2]);
                acc[j][3] = ffma2(wj, xp3, acc[j][3]);
            }
        }
        __syncthreads();
    }
#pragma unroll
    for (int j = 0; j < 4; j++) {
        int o = oq * 4 + j;
        float bv = b_out[o];
#pragma unroll
        for (int p = 0; p < 4; p++) {
            float lo, hi;
            unpack2(acc[j][p], lo, hi);
            int b0 = bq * 8 + 2 * p;
            out[((size_t)t * B_ + b0) * OUT_ + o] = lo + bv;
            out[((size_t)t * B_ + b0 + 1) * OUT_ + o] = hi + bv;
        }
    }
}

// ---------------- launcher ----------------
extern "C" void kernel_launch(void* const* d_in, const int* in_sizes, int n_in,
                              void* d_out, int out_size) {
    const float* x     = (const float*)d_in[0];
    const float* W_ih  = (const float*)d_in[1];
    const float* W_hh  = (const float*)d_in[2];
    const float* b_ih  = (const float*)d_in[3];
    const float* b_hh  = (const float*)d_in[4];
    const float* W_out = (const float*)d_in[5];
    const float* b_out = (const float*)d_in[6];
    float* out = (float*)d_out;

    cudaFuncSetAttribute(k_rec, cudaFuncAttributeMaxDynamicSharedMemorySize, REC_SMEM);
    cudaFuncSetAttribute(k_out, cudaFuncAttributeMaxDynamicSharedMemorySize, OUT_SMEM);

    k_init<<<1, 1>>>();
    k_xg<<<dim3(HCN_, T_), 256>>>(x, W_ih, b_ih, b_hh);
    k_rec<<<BG_ * HCN_, 512, REC_SMEM>>>(W_hh);
    k_out<<<T_, 256, OUT_SMEM>>>(W_out, b_out, out);
}